// round 5
// baseline (speedup 1.0000x reference)
#include <cuda_runtime.h>

#define NTOK 4096
#define DM   512
#define DPE  16
#define NH   8
#define HD   64
#define QK_SCALE 0.125f   // 64^-0.5

// Scratch (no allocations allowed)
__device__ float g_Q[NH * NTOK * HD];   // [h][n][d]
__device__ float g_K[NH * NTOK * HD];
__device__ float g_V[NH * NTOK * HD];
__device__ float g_peb[NH * NTOK];      // [h][n] : pe projection (key-side bias)
__device__ float g_AO[NTOK * DM];       // attention output, [n][h*64+d]

// ---------------------------------------------------------------------------
// Tiled SGEMM: C[M x NCOLS] = A[M x 512] * B[512 x NCOLS] + bias
// BM=BN=64, BK=16, 256 threads, 4x4 microtile per thread.
// QKV_SCATTER: col-block bn maps to (part = bn/8, head = bn%8); write into
// g_Q/g_K/g_V with per-head layout. Otherwise write row-major into C.
// A_FROM_GAO: ignore the A argument and read the device-global g_AO
// (device symbols must NOT be passed from host code).
// ---------------------------------------------------------------------------
template <int NCOLS, bool QKV_SCATTER, bool A_FROM_GAO>
__global__ __launch_bounds__(256) void gemm64(const float* __restrict__ Ain,
                                              const float* __restrict__ B,
                                              const float* __restrict__ bias,
                                              float* __restrict__ C) {
    __shared__ float As[16][68];   // A^T tile, padded rows (272B = 16B-aligned)
    __shared__ float Bs[16][64];

    const float* A = A_FROM_GAO ? g_AO : Ain;

    const int row0 = blockIdx.x * 64;
    const int col0 = blockIdx.y * 64;
    const int tid  = threadIdx.x;
    const int tx   = tid & 15;     // output col group
    const int ty   = tid >> 4;     // output row group

    float acc[4][4] = {};

    for (int k0 = 0; k0 < DM; k0 += 16) {
        // A tile 64x16: one float4 per thread, transposed into As
        {
            const int r  = tid >> 2;
            const int c4 = (tid & 3) << 2;
            float4 a = *(const float4*)&A[(row0 + r) * DM + k0 + c4];
            As[c4 + 0][r] = a.x;
            As[c4 + 1][r] = a.y;
            As[c4 + 2][r] = a.z;
            As[c4 + 3][r] = a.w;
        }
        // B tile 16x64: one float4 per thread
        {
            const int r  = tid >> 4;
            const int c4 = (tid & 15) << 2;
            *(float4*)&Bs[r][c4] = *(const float4*)&B[(k0 + r) * NCOLS + col0 + c4];
        }
        __syncthreads();

#pragma unroll
        for (int k = 0; k < 16; k++) {
            float4 a  = *(const float4*)&As[k][ty * 4];
            float4 bv = *(const float4*)&Bs[k][tx * 4];
            float av[4] = {a.x, a.y, a.z, a.w};
            float bb[4] = {bv.x, bv.y, bv.z, bv.w};
#pragma unroll
            for (int i = 0; i < 4; i++)
#pragma unroll
                for (int j = 0; j < 4; j++) acc[i][j] += av[i] * bb[j];
        }
        __syncthreads();
    }

    if (QKV_SCATTER) {
        const int part = blockIdx.y >> 3;   // 0=Q, 1=K, 2=V
        const int h    = blockIdx.y & 7;
        float* dst = (part == 0) ? g_Q : (part == 1) ? g_K : g_V;
#pragma unroll
        for (int i = 0; i < 4; i++) {
            const int r = row0 + ty * 4 + i;
#pragma unroll
            for (int j = 0; j < 4; j++) {
                const int d = tx * 4 + j;
                dst[(h * NTOK + r) * HD + d] = acc[i][j] + bias[col0 + d];
            }
        }
    } else {
#pragma unroll
        for (int i = 0; i < 4; i++) {
            const int r = row0 + ty * 4 + i;
#pragma unroll
            for (int j = 0; j < 4; j++) {
                const int c = col0 + tx * 4 + j;
                C[r * NCOLS + c] = acc[i][j] + bias[c];
            }
        }
    }
}

// ---------------------------------------------------------------------------
// pe projection: peb[h][n] = sum_k pe[n][k] * w_pe[k][h] + b_pe[h]
// ---------------------------------------------------------------------------
__global__ void pe_proj(const float* __restrict__ pe,
                        const float* __restrict__ wpe,
                        const float* __restrict__ bpe) {
    const int n = blockIdx.x * 256 + threadIdx.x;
    if (n >= NTOK) return;
    float pv[DPE];
#pragma unroll
    for (int k = 0; k < DPE; k++) pv[k] = pe[n * DPE + k];
#pragma unroll
    for (int h = 0; h < NH; h++) {
        float s = bpe[h];
#pragma unroll
        for (int k = 0; k < DPE; k++) s += pv[k] * wpe[k * NH + h];
        g_peb[h * NTOK + n] = s;
    }
}

// ---------------------------------------------------------------------------
// Flash attention. bias[h,i,j] = p[j,h] - p[i,h]; the -p[i,h] term is
// constant over the softmax axis j, so it cancels: only the per-key bias
// p[j,h] matters. 128 threads/CTA, one query row per thread, head =
// blockIdx.y. K/V streamed through 32x64 smem tiles; online softmax with
// per-chunk max.
// ---------------------------------------------------------------------------
__global__ __launch_bounds__(128) void attn_kernel() {
    __shared__ float Ks[32 * HD];
    __shared__ float Vs[32 * HD];
    __shared__ float pb[32];

    const int h   = blockIdx.y;
    const int tid = threadIdx.x;
    const int i   = blockIdx.x * 128 + tid;   // query row

    // q row -> registers
    float q[HD];
    {
        const float* qg = &g_Q[(h * NTOK + i) * HD];
#pragma unroll
        for (int k4 = 0; k4 < 16; k4++) {
            float4 t = *(const float4*)&qg[k4 * 4];
            q[k4 * 4 + 0] = t.x; q[k4 * 4 + 1] = t.y;
            q[k4 * 4 + 2] = t.z; q[k4 * 4 + 3] = t.w;
        }
    }

    float acc[HD];
#pragma unroll
    for (int d = 0; d < HD; d++) acc[d] = 0.f;
    float m = -1e30f, l = 0.f;

    const float* Kg = &g_K[h * NTOK * HD];
    const float* Vg = &g_V[h * NTOK * HD];
    const float* pg = &g_peb[h * NTOK];

    for (int j0 = 0; j0 < NTOK; j0 += 32) {
        // cooperative tile load: 2048 floats each = 512 float4, 128 thr x 4
#pragma unroll
        for (int t = 0; t < 4; t++) {
            const int idx = tid + t * 128;
            ((float4*)Ks)[idx] = ((const float4*)(Kg + j0 * HD))[idx];
            ((float4*)Vs)[idx] = ((const float4*)(Vg + j0 * HD))[idx];
        }
        if (tid < 32) pb[tid] = pg[j0 + tid];
        __syncthreads();

        // scores for this chunk
        float s[32];
#pragma unroll
        for (int j = 0; j < 32; j++) {
            float p0 = 0.f, p1 = 0.f, p2 = 0.f, p3 = 0.f;
            const float4* kr = (const float4*)&Ks[j * HD];
#pragma unroll
            for (int k4 = 0; k4 < 16; k4++) {
                float4 kv = kr[k4];
                p0 += q[k4 * 4 + 0] * kv.x;
                p1 += q[k4 * 4 + 1] * kv.y;
                p2 += q[k4 * 4 + 2] * kv.z;
                p3 += q[k4 * 4 + 3] * kv.w;
            }
            s[j] = ((p0 + p1) + (p2 + p3)) * QK_SCALE + pb[j];
        }

        // online softmax update
        float mc = s[0];
#pragma unroll
        for (int j = 1; j < 32; j++) mc = fmaxf(mc, s[j]);
        const float mnew  = fmaxf(m, mc);
        const float alpha = __expf(m - mnew);
        m = mnew;
        l *= alpha;
#pragma unroll
        for (int d = 0; d < HD; d++) acc[d] *= alpha;

#pragma unroll
        for (int j = 0; j < 32; j++) {
            const float p = __expf(s[j] - m);
            l += p;
            const float4* vr = (const float4*)&Vs[j * HD];
#pragma unroll
            for (int k4 = 0; k4 < 16; k4++) {
                float4 vv = vr[k4];
                acc[k4 * 4 + 0] += p * vv.x;
                acc[k4 * 4 + 1] += p * vv.y;
                acc[k4 * 4 + 2] += p * vv.z;
                acc[k4 * 4 + 3] += p * vv.w;
            }
        }
        __syncthreads();
    }

    const float inv = 1.f / l;
    float* og = &g_AO[i * DM + h * HD];
#pragma unroll
    for (int k4 = 0; k4 < 16; k4++) {
        float4 o;
        o.x = acc[k4 * 4 + 0] * inv;
        o.y = acc[k4 * 4 + 1] * inv;
        o.z = acc[k4 * 4 + 2] * inv;
        o.w = acc[k4 * 4 + 3] * inv;
        *(float4*)&og[k4 * 4] = o;
    }
}

// ---------------------------------------------------------------------------
extern "C" void kernel_launch(void* const* d_in, const int* in_sizes, int n_in,
                              void* d_out, int out_size) {
    const float* x     = (const float*)d_in[0];
    const float* pe    = (const float*)d_in[1];
    const float* w_qkv = (const float*)d_in[2];
    const float* b_qkv = (const float*)d_in[3];
    const float* w_pe  = (const float*)d_in[4];
    const float* b_pe  = (const float*)d_in[5];
    const float* w_out = (const float*)d_in[6];
    const float* b_out = (const float*)d_in[7];
    float* out = (float*)d_out;

    // QKV projection: 4096x1536 = 64 row-blocks x 24 col-blocks
    gemm64<3 * DM, true, false><<<dim3(64, 24), 256>>>(x, w_qkv, b_qkv, nullptr);

    // pe projection (key-side softmax bias)
    pe_proj<<<NTOK / 256, 256>>>(pe, w_pe, b_pe);

    // flash attention: 32 query blocks x 8 heads
    attn_kernel<<<dim3(32, NH), 128>>>();

    // output projection: A comes from device-global g_AO (selected in device
    // code -- do NOT pass a __device__ symbol from host)
    gemm64<DM, false, true><<<dim3(64, 8), 256>>>(nullptr, w_out, b_out, out);
}

// round 8
// speedup vs baseline: 3.3520x; 3.3520x over previous
#include <cuda_runtime.h>
#include <cstdint>

#define NTOK 4096
#define DM   512
#define DPE  16
#define NH   8
#define HD   64
#define QK_SCALE 0.125f   // 64^-0.5

// Scratch (no allocations allowed)
__device__ float g_Q[NH * NTOK * HD];   // [h][n][d]
__device__ float g_K[NH * NTOK * HD];
__device__ float g_V[NH * NTOK * HD];
__device__ float g_peb[NH * NTOK];      // [h][n] : key-side softmax bias
__device__ float g_AO[NTOK * DM];       // attention output, [n][h*64+d]

// ---------------------------------------------------------------------------
// TF32 helpers
// ---------------------------------------------------------------------------
__device__ __forceinline__ uint32_t f2tf32(float f) {
    uint32_t r;
    asm("cvt.rna.tf32.f32 %0, %1;" : "=r"(r) : "f"(f));
    return r;
}

// D += A(m16 x k8) * B(k8 x n8), tf32 inputs, fp32 accum.
// a0:(g,t) a1:(g+8,t) a2:(g,t+4) a3:(g+8,t+4); b0:(t,g) b1:(t+4,g)
// c0:(g,2t) c1:(g,2t+1) c2:(g+8,2t) c3:(g+8,2t+1)   [g=lane>>2, t=lane&3]
__device__ __forceinline__ void mma_tf32(float d[4], const uint32_t a[4],
                                         const uint32_t b[2]) {
    asm("mma.sync.aligned.m16n8k8.row.col.f32.tf32.tf32.f32 "
        "{%0,%1,%2,%3}, {%4,%5,%6,%7}, {%8,%9}, {%0,%1,%2,%3};"
        : "+f"(d[0]), "+f"(d[1]), "+f"(d[2]), "+f"(d[3])
        : "r"(a[0]), "r"(a[1]), "r"(a[2]), "r"(a[3]), "r"(b[0]), "r"(b[1]));
}

// ---------------------------------------------------------------------------
// TF32 tensor-core GEMM: C[M x NCOLS] = A[M x 512] * B[512 x NCOLS] + bias
// Block tile 128x64, 8 warps (4m x 2n), warp tile 32x32, BK=16.
// Smem strides chosen conflict-free for fragment LDS (A:20 -> 4g+t,
// B:72 -> 8t+g patterns mod 32).
// ---------------------------------------------------------------------------
template <int NCOLS, bool QKV_SCATTER, bool A_FROM_GAO>
__global__ __launch_bounds__(256) void gemm_mma(const float* __restrict__ Ain,
                                                const float* __restrict__ B,
                                                const float* __restrict__ bias,
                                                float* __restrict__ C) {
    __shared__ uint32_t As[128 * 20];   // [row][k], stride 20
    __shared__ uint32_t Bs[16 * 72];    // [k][col], stride 72

    const float* A = A_FROM_GAO ? g_AO : Ain;

    const int row0 = blockIdx.x * 128;
    const int col0 = blockIdx.y * 64;
    const int tid  = threadIdx.x;
    const int warp = tid >> 5;
    const int lane = tid & 31;
    const int g    = lane >> 2;
    const int t    = lane & 3;
    const int wm   = (warp >> 1) * 32;   // warp row offset (0,32,64,96)
    const int wn   = (warp & 1) * 32;    // warp col offset (0,32)

    float acc[2][4][4];
#pragma unroll
    for (int mt = 0; mt < 2; mt++)
#pragma unroll
        for (int nt = 0; nt < 4; nt++)
#pragma unroll
            for (int c = 0; c < 4; c++) acc[mt][nt][c] = 0.f;

    for (int k0 = 0; k0 < DM; k0 += 16) {
        // stage A tile 128x16 (512 float4, 2 per thread), cvt to tf32
#pragma unroll
        for (int ii = 0; ii < 2; ii++) {
            const int id = tid + ii * 256;
            const int r  = id >> 2;
            const int c4 = (id & 3) << 2;
            float4 a = *(const float4*)&A[(row0 + r) * DM + k0 + c4];
            As[r * 20 + c4 + 0] = f2tf32(a.x);
            As[r * 20 + c4 + 1] = f2tf32(a.y);
            As[r * 20 + c4 + 2] = f2tf32(a.z);
            As[r * 20 + c4 + 3] = f2tf32(a.w);
        }
        // stage B tile 16x64 (256 float4, 1 per thread)
        {
            const int r  = tid >> 4;
            const int c4 = (tid & 15) << 2;
            float4 b = *(const float4*)&B[(k0 + r) * NCOLS + col0 + c4];
            Bs[r * 72 + c4 + 0] = f2tf32(b.x);
            Bs[r * 72 + c4 + 1] = f2tf32(b.y);
            Bs[r * 72 + c4 + 2] = f2tf32(b.z);
            Bs[r * 72 + c4 + 3] = f2tf32(b.w);
        }
        __syncthreads();

#pragma unroll
        for (int ks = 0; ks < 16; ks += 8) {
            uint32_t af[2][4];
#pragma unroll
            for (int mt = 0; mt < 2; mt++) {
                const int r0 = wm + mt * 16 + g;
                af[mt][0] = As[(r0 + 0) * 20 + ks + t];
                af[mt][1] = As[(r0 + 8) * 20 + ks + t];
                af[mt][2] = As[(r0 + 0) * 20 + ks + t + 4];
                af[mt][3] = As[(r0 + 8) * 20 + ks + t + 4];
            }
            uint32_t bf[4][2];
#pragma unroll
            for (int nt = 0; nt < 4; nt++) {
                const int c = wn + nt * 8 + g;
                bf[nt][0] = Bs[(ks + t) * 72 + c];
                bf[nt][1] = Bs[(ks + t + 4) * 72 + c];
            }
#pragma unroll
            for (int mt = 0; mt < 2; mt++)
#pragma unroll
                for (int nt = 0; nt < 4; nt++)
                    mma_tf32(acc[mt][nt], af[mt], bf[nt]);
        }
        __syncthreads();
    }

    // epilogue
#pragma unroll
    for (int mt = 0; mt < 2; mt++) {
#pragma unroll
        for (int nt = 0; nt < 4; nt++) {
            const int cc = wn + nt * 8 + 2 * t;          // col within 64-block
            const float b0 = bias[col0 + cc];
            const float b1 = bias[col0 + cc + 1];
            const int r0 = row0 + wm + mt * 16 + g;
            if (QKV_SCATTER) {
                const int part = blockIdx.y >> 3;        // 0=Q,1=K,2=V
                const int h    = blockIdx.y & 7;
                float* dst = (part == 0) ? g_Q : (part == 1) ? g_K : g_V;
                float2 v0 = {acc[mt][nt][0] + b0, acc[mt][nt][1] + b1};
                float2 v1 = {acc[mt][nt][2] + b0, acc[mt][nt][3] + b1};
                *(float2*)&dst[((size_t)h * NTOK + r0) * HD + cc]     = v0;
                *(float2*)&dst[((size_t)h * NTOK + r0 + 8) * HD + cc] = v1;
            } else {
                const int c = col0 + cc;
                float2 v0 = {acc[mt][nt][0] + b0, acc[mt][nt][1] + b1};
                float2 v1 = {acc[mt][nt][2] + b0, acc[mt][nt][3] + b1};
                *(float2*)&C[(size_t)r0 * NCOLS + c]       = v0;
                *(float2*)&C[(size_t)(r0 + 8) * NCOLS + c] = v1;
            }
        }
    }
}

// ---------------------------------------------------------------------------
// pe projection: peb[h][n] = sum_k pe[n][k] * w_pe[k][h] + b_pe[h]
// ---------------------------------------------------------------------------
__global__ void pe_proj(const float* __restrict__ pe,
                        const float* __restrict__ wpe,
                        const float* __restrict__ bpe) {
    const int n = blockIdx.x * 256 + threadIdx.x;
    if (n >= NTOK) return;
    float pv[DPE];
#pragma unroll
    for (int k = 0; k < DPE; k++) pv[k] = pe[n * DPE + k];
#pragma unroll
    for (int h = 0; h < NH; h++) {
        float s = bpe[h];
#pragma unroll
        for (int k = 0; k < DPE; k++) s += pv[k] * wpe[k * NH + h];
        g_peb[h * NTOK + n] = s;
    }
}

// ---------------------------------------------------------------------------
// TF32 tensor-core flash attention.
// bias[h,i,j] = p[j,h] - p[i,h]; -p[i,h] is constant over softmax axis j and
// cancels -> per-key bias p[j,h] only.
// CTA: 256 thr = 8 warps, 128 query rows (16 per warp), one head per
// blockIdx.y. Keys streamed in 32-wide chunks. Q fragments resident in regs.
// Smem strides 68/72/36 make every fragment LDS bank-conflict-free.
// ---------------------------------------------------------------------------
__global__ __launch_bounds__(256) void attn_mma() {
    __shared__ uint32_t Ks[32 * 68];        // [key][feat]  stride 68
    __shared__ uint32_t Vs[32 * 72];        // [key][feat]  stride 72
    __shared__ uint32_t Ps[8][16 * 36];     // per-warp P   [row][key] stride 36
    __shared__ float    pb[32];

    const int h    = blockIdx.y;
    const int tid  = threadIdx.x;
    const int warp = tid >> 5;
    const int lane = tid & 31;
    const int g    = lane >> 2;
    const int t    = lane & 3;
    const int qr0  = blockIdx.x * 128 + warp * 16;   // this warp's query base

    const float* Qg = &g_Q[(size_t)h * NTOK * HD];
    const float* Kg = &g_K[(size_t)h * NTOK * HD];
    const float* Vg = &g_V[(size_t)h * NTOK * HD];
    const float* pg = &g_peb[h * NTOK];

    // Q fragments, resident for the whole kernel: 8 k-steps x 4 regs
    uint32_t aq[8][4];
#pragma unroll
    for (int ks = 0; ks < 8; ks++) {
        const int c = ks * 8 + t;
        aq[ks][0] = f2tf32(Qg[(qr0 + g) * HD + c]);
        aq[ks][1] = f2tf32(Qg[(qr0 + g + 8) * HD + c]);
        aq[ks][2] = f2tf32(Qg[(qr0 + g) * HD + c + 4]);
        aq[ks][3] = f2tf32(Qg[(qr0 + g + 8) * HD + c + 4]);
    }

    float oacc[8][4];
#pragma unroll
    for (int nt = 0; nt < 8; nt++)
#pragma unroll
        for (int c = 0; c < 4; c++) oacc[nt][c] = 0.f;
    float m0 = -1e30f, m1 = -1e30f, l0 = 0.f, l1 = 0.f;

    for (int j0 = 0; j0 < NTOK; j0 += 32) {
        // stage K/V: 32x64 each = 512 float4, 2 per thread per tensor
#pragma unroll
        for (int ii = 0; ii < 2; ii++) {
            const int id  = tid + ii * 256;
            const int row = id >> 4;
            const int c4  = (id & 15) << 2;
            float4 kv = *(const float4*)&Kg[(j0 + row) * HD + c4];
            Ks[row * 68 + c4 + 0] = f2tf32(kv.x);
            Ks[row * 68 + c4 + 1] = f2tf32(kv.y);
            Ks[row * 68 + c4 + 2] = f2tf32(kv.z);
            Ks[row * 68 + c4 + 3] = f2tf32(kv.w);
            float4 vv = *(const float4*)&Vg[(j0 + row) * HD + c4];
            Vs[row * 72 + c4 + 0] = f2tf32(vv.x);
            Vs[row * 72 + c4 + 1] = f2tf32(vv.y);
            Vs[row * 72 + c4 + 2] = f2tf32(vv.z);
            Vs[row * 72 + c4 + 3] = f2tf32(vv.w);
        }
        if (tid < 32) pb[tid] = pg[j0 + tid];
        __syncthreads();

        // S = Q K^T for 16 rows x 32 keys
        float sacc[4][4];
#pragma unroll
        for (int nt = 0; nt < 4; nt++)
#pragma unroll
            for (int c = 0; c < 4; c++) sacc[nt][c] = 0.f;
#pragma unroll
        for (int ks = 0; ks < 8; ks++) {
#pragma unroll
            for (int nt = 0; nt < 4; nt++) {
                uint32_t bf[2];
                const int key = nt * 8 + g;
                bf[0] = Ks[key * 68 + ks * 8 + t];
                bf[1] = Ks[key * 68 + ks * 8 + t + 4];
                mma_tf32(sacc[nt], aq[ks], bf);
            }
        }

        // scale + bias, chunk max
        float ps[4][4];
        float mx0 = -1e30f, mx1 = -1e30f;
#pragma unroll
        for (int nt = 0; nt < 4; nt++) {
            const int c0 = nt * 8 + 2 * t;
            const float pb0 = pb[c0], pb1 = pb[c0 + 1];
            ps[nt][0] = fmaf(sacc[nt][0], QK_SCALE, pb0);
            ps[nt][1] = fmaf(sacc[nt][1], QK_SCALE, pb1);
            ps[nt][2] = fmaf(sacc[nt][2], QK_SCALE, pb0);
            ps[nt][3] = fmaf(sacc[nt][3], QK_SCALE, pb1);
            mx0 = fmaxf(mx0, fmaxf(ps[nt][0], ps[nt][1]));
            mx1 = fmaxf(mx1, fmaxf(ps[nt][2], ps[nt][3]));
        }
        mx0 = fmaxf(mx0, __shfl_xor_sync(0xffffffffu, mx0, 1));
        mx0 = fmaxf(mx0, __shfl_xor_sync(0xffffffffu, mx0, 2));
        mx1 = fmaxf(mx1, __shfl_xor_sync(0xffffffffu, mx1, 1));
        mx1 = fmaxf(mx1, __shfl_xor_sync(0xffffffffu, mx1, 2));

        const float mn0 = fmaxf(m0, mx0);
        const float mn1 = fmaxf(m1, mx1);
        const float al0 = __expf(m0 - mn0);
        const float al1 = __expf(m1 - mn1);
        m0 = mn0; m1 = mn1;

        // P = exp(s - m), row sums, stash P (tf32) in per-warp smem
        float rs0 = 0.f, rs1 = 0.f;
        uint32_t* Pw = Ps[warp];
#pragma unroll
        for (int nt = 0; nt < 4; nt++) {
            const int c0 = nt * 8 + 2 * t;
            float p00 = __expf(ps[nt][0] - m0);
            float p01 = __expf(ps[nt][1] - m0);
            float p10 = __expf(ps[nt][2] - m1);
            float p11 = __expf(ps[nt][3] - m1);
            rs0 += p00 + p01;
            rs1 += p10 + p11;
            Pw[g * 36 + c0]           = f2tf32(p00);
            Pw[g * 36 + c0 + 1]       = f2tf32(p01);
            Pw[(g + 8) * 36 + c0]     = f2tf32(p10);
            Pw[(g + 8) * 36 + c0 + 1] = f2tf32(p11);
        }
        rs0 += __shfl_xor_sync(0xffffffffu, rs0, 1);
        rs0 += __shfl_xor_sync(0xffffffffu, rs0, 2);
        rs1 += __shfl_xor_sync(0xffffffffu, rs1, 1);
        rs1 += __shfl_xor_sync(0xffffffffu, rs1, 2);
        l0 = l0 * al0 + rs0;
        l1 = l1 * al1 + rs1;

        // rescale O accumulators
#pragma unroll
        for (int nt = 0; nt < 8; nt++) {
            oacc[nt][0] *= al0; oacc[nt][1] *= al0;
            oacc[nt][2] *= al1; oacc[nt][3] *= al1;
        }
        __syncwarp();   // Ps visible within the warp

        // O += P(16x32) * V(32x64)
#pragma unroll
        for (int kk = 0; kk < 4; kk++) {
            uint32_t pa[4];
            pa[0] = Pw[g * 36 + kk * 8 + t];
            pa[1] = Pw[(g + 8) * 36 + kk * 8 + t];
            pa[2] = Pw[g * 36 + kk * 8 + t + 4];
            pa[3] = Pw[(g + 8) * 36 + kk * 8 + t + 4];
#pragma unroll
            for (int nt = 0; nt < 8; nt++) {
                uint32_t bf[2];
                bf[0] = Vs[(kk * 8 + t) * 72 + nt * 8 + g];
                bf[1] = Vs[(kk * 8 + t + 4) * 72 + nt * 8 + g];
                mma_tf32(oacc[nt], pa, bf);
            }
        }
        __syncthreads();   // protect Ks/Vs before next stage
    }

    // normalize + write to g_AO
    const float inv0 = 1.f / l0;
    const float inv1 = 1.f / l1;
#pragma unroll
    for (int nt = 0; nt < 8; nt++) {
        const int d = nt * 8 + 2 * t;
        float2 v0 = {oacc[nt][0] * inv0, oacc[nt][1] * inv0};
        float2 v1 = {oacc[nt][2] * inv1, oacc[nt][3] * inv1};
        *(float2*)&g_AO[(size_t)(qr0 + g) * DM + h * HD + d]     = v0;
        *(float2*)&g_AO[(size_t)(qr0 + g + 8) * DM + h * HD + d] = v1;
    }
}

// ---------------------------------------------------------------------------
extern "C" void kernel_launch(void* const* d_in, const int* in_sizes, int n_in,
                              void* d_out, int out_size) {
    const float* x     = (const float*)d_in[0];
    const float* pe    = (const float*)d_in[1];
    const float* w_qkv = (const float*)d_in[2];
    const float* b_qkv = (const float*)d_in[3];
    const float* w_pe  = (const float*)d_in[4];
    const float* b_pe  = (const float*)d_in[5];
    const float* w_out = (const float*)d_in[6];
    const float* b_out = (const float*)d_in[7];
    float* out = (float*)d_out;

    // QKV projection: 4096x1536, blocks 128x64 -> (32, 24)
    gemm_mma<3 * DM, true, false><<<dim3(32, 24), 256>>>(x, w_qkv, b_qkv, nullptr);

    // pe projection (key-side softmax bias)
    pe_proj<<<NTOK / 256, 256>>>(pe, w_pe, b_pe);

    // flash attention: 32 query blocks x 8 heads
    attn_mma<<<dim3(32, NH), 256>>>();

    // output projection: 4096x512 -> (32, 8); A = g_AO selected in device code
    gemm_mma<DM, false, true><<<dim3(32, 8), 256>>>(nullptr, w_out, b_out, out);
}

// round 9
// speedup vs baseline: 4.9781x; 1.4851x over previous
#include <cuda_runtime.h>
#include <cuda_fp16.h>
#include <cstdint>

#define NTOK 4096
#define DM   512
#define DPE  16
#define NH   8
#define HD   64
#define QK_SCALE 0.125f   // 64^-0.5

// Scratch (no allocations allowed)
__device__ __half g_Q[NH * NTOK * HD];   // [h][n][d]  fp16
__device__ __half g_K[NH * NTOK * HD];
__device__ __half g_V[NH * NTOK * HD];
__device__ float  g_peb[NH * NTOK];      // [h][n] key-side softmax bias
__device__ float  g_AO[NTOK * DM];       // attention output, [n][h*64+d]

// ---------------------------------------------------------------------------
// fp16 mma helpers. m16n8k16 row.col, f32 accum.
// A (16x16): a0=(g,2t),(g,2t+1)  a1=(g+8,2t..)  a2=(g,2t+8..)  a3=(g+8,2t+8..)
// B (16x8):  b0=(2t,g),(2t+1,g)  b1=(2t+8,g),(2t+9,g)
// C: c0=(g,2t) c1=(g,2t+1) c2=(g+8,2t) c3=(g+8,2t+1)     [g=lane>>2, t=lane&3]
// ---------------------------------------------------------------------------
__device__ __forceinline__ void mma_f16(float d[4], const uint32_t a[4],
                                        const uint32_t b[2]) {
    asm("mma.sync.aligned.m16n8k16.row.col.f32.f16.f16.f32 "
        "{%0,%1,%2,%3}, {%4,%5,%6,%7}, {%8,%9}, {%0,%1,%2,%3};"
        : "+f"(d[0]), "+f"(d[1]), "+f"(d[2]), "+f"(d[3])
        : "r"(a[0]), "r"(a[1]), "r"(a[2]), "r"(a[3]), "r"(b[0]), "r"(b[1]));
}

__device__ __forceinline__ uint32_t pack2(float lo, float hi) {
    __half2 h = __floats2half2_rn(lo, hi);
    return *reinterpret_cast<uint32_t*>(&h);
}

// ---------------------------------------------------------------------------
// fp16 tensor-core GEMM: C[M x NCOLS] = A[M x 512] * B[512 x NCOLS] + bias
// Block 128x64, 8 warps (4m x 2n), warp tile 32x32, BK=16.
// A staged [row][k] fp16 stride 24 halves (12 words ≡ 12 mod 32: conflict-free
// a-frag LDS). B staged transposed [n][k] stride 24 halves (same property).
// ---------------------------------------------------------------------------
template <int NCOLS, bool QKV_SCATTER, bool A_FROM_GAO>
__global__ __launch_bounds__(256) void gemm_mma(const float* __restrict__ Ain,
                                                const float* __restrict__ B,
                                                const float* __restrict__ bias,
                                                float* __restrict__ C) {
    __shared__ __half As[128 * 24];   // [row][k]
    __shared__ __half Bt[64 * 24];    // [col][k]

    const float* A = A_FROM_GAO ? g_AO : Ain;

    const int row0 = blockIdx.x * 128;
    const int col0 = blockIdx.y * 64;
    const int tid  = threadIdx.x;
    const int warp = tid >> 5;
    const int lane = tid & 31;
    const int g    = lane >> 2;
    const int t    = lane & 3;
    const int wm   = (warp >> 1) * 32;
    const int wn   = (warp & 1) * 32;

    const uint32_t* Asw = (const uint32_t*)As;
    const uint32_t* Btw = (const uint32_t*)Bt;

    float acc[2][4][4];
#pragma unroll
    for (int mt = 0; mt < 2; mt++)
#pragma unroll
        for (int nt = 0; nt < 4; nt++)
#pragma unroll
            for (int c = 0; c < 4; c++) acc[mt][nt][c] = 0.f;

    for (int k0 = 0; k0 < DM; k0 += 16) {
        // stage A 128x16 -> fp16 (2048 floats, 512 float4, 2/thread)
#pragma unroll
        for (int ii = 0; ii < 2; ii++) {
            const int id = tid + ii * 256;
            const int r  = id >> 2;
            const int c4 = (id & 3) << 2;
            float4 a = *(const float4*)&A[(size_t)(row0 + r) * DM + k0 + c4];
            uint2 p;
            p.x = pack2(a.x, a.y);
            p.y = pack2(a.z, a.w);
            *(uint2*)&As[r * 24 + c4] = p;
        }
        // stage B 16x64 transposed -> Bt[col][k]
        // mapping: per warp 8 cols x 4 kp -> conflict-free STS (word 12n+kp)
#pragma unroll
        for (int ii = 0; ii < 2; ii++) {
            const int id = tid + ii * 256;
            const int n  = (id & 7) + ((id >> 6) << 3);   // 0..63
            const int kp = (id >> 3) & 7;                 // 0..7 (k pair)
            const float blo = B[(size_t)(k0 + 2 * kp) * NCOLS + col0 + n];
            const float bhi = B[(size_t)(k0 + 2 * kp + 1) * NCOLS + col0 + n];
            *(uint32_t*)&Bt[n * 24 + 2 * kp] = pack2(blo, bhi);
        }
        __syncthreads();

        // fragments + 8 mma (one k16 step per tile)
        uint32_t af[2][4];
#pragma unroll
        for (int mt = 0; mt < 2; mt++) {
            const int r = wm + mt * 16 + g;
            af[mt][0] = Asw[r * 12 + t];
            af[mt][1] = Asw[(r + 8) * 12 + t];
            af[mt][2] = Asw[r * 12 + t + 4];
            af[mt][3] = Asw[(r + 8) * 12 + t + 4];
        }
        uint32_t bf[4][2];
#pragma unroll
        for (int nt = 0; nt < 4; nt++) {
            const int c = wn + nt * 8 + g;
            bf[nt][0] = Btw[c * 12 + t];
            bf[nt][1] = Btw[c * 12 + t + 4];
        }
#pragma unroll
        for (int mt = 0; mt < 2; mt++)
#pragma unroll
            for (int nt = 0; nt < 4; nt++)
                mma_f16(acc[mt][nt], af[mt], bf[nt]);
        __syncthreads();
    }

    // epilogue
#pragma unroll
    for (int mt = 0; mt < 2; mt++) {
#pragma unroll
        for (int nt = 0; nt < 4; nt++) {
            const int cc = wn + nt * 8 + 2 * t;
            const float b0 = bias[col0 + cc];
            const float b1 = bias[col0 + cc + 1];
            const int r0 = row0 + wm + mt * 16 + g;
            if (QKV_SCATTER) {
                const int part = blockIdx.y >> 3;        // 0=Q,1=K,2=V
                const int h    = blockIdx.y & 7;
                __half* dst = (part == 0) ? g_Q : (part == 1) ? g_K : g_V;
                *(uint32_t*)&dst[((size_t)h * NTOK + r0) * HD + cc] =
                    pack2(acc[mt][nt][0] + b0, acc[mt][nt][1] + b1);
                *(uint32_t*)&dst[((size_t)h * NTOK + r0 + 8) * HD + cc] =
                    pack2(acc[mt][nt][2] + b0, acc[mt][nt][3] + b1);
            } else {
                const int c = col0 + cc;
                float2 v0 = {acc[mt][nt][0] + b0, acc[mt][nt][1] + b1};
                float2 v1 = {acc[mt][nt][2] + b0, acc[mt][nt][3] + b1};
                *(float2*)&C[(size_t)r0 * NCOLS + c]       = v0;
                *(float2*)&C[(size_t)(r0 + 8) * NCOLS + c] = v1;
            }
        }
    }
}

// ---------------------------------------------------------------------------
// pe projection: peb[h][n] = sum_k pe[n][k] * w_pe[k][h] + b_pe[h]
// ---------------------------------------------------------------------------
__global__ void pe_proj(const float* __restrict__ pe,
                        const float* __restrict__ wpe,
                        const float* __restrict__ bpe) {
    const int n = blockIdx.x * 256 + threadIdx.x;
    if (n >= NTOK) return;
    float pv[DPE];
#pragma unroll
    for (int k = 0; k < DPE; k++) pv[k] = pe[n * DPE + k];
#pragma unroll
    for (int h = 0; h < NH; h++) {
        float s = bpe[h];
#pragma unroll
        for (int k = 0; k < DPE; k++) s += pv[k] * wpe[k * NH + h];
        g_peb[h * NTOK + n] = s;
    }
}

// ---------------------------------------------------------------------------
// fp16 tensor-core flash attention.
// bias[h,i,j] = p[j,h] - p[i,h]: -p[i,h] cancels in softmax over j -> only a
// per-key bias p[j,h] remains.
// CTA: 256 thr / 8 warps, 128 query rows (16/warp), head = blockIdx.y.
// 64-key chunks. S's C-fragment layout IS the PV A-fragment layout for fp16
// m16n8k16, so P never leaves registers (no smem round-trip).
// K staged [key][feat] (natural b-frags), V staged transposed [feat][key].
// Stride 72 halves = 36 words ≡ 4 mod 32 -> all fragment LDS conflict-free.
// ---------------------------------------------------------------------------
__global__ __launch_bounds__(256, 2) void attn_mma() {
    __shared__ __half Ks[64 * 72];     // [key][feat]
    __shared__ __half Vt[64 * 72];     // [feat][key]
    __shared__ float  pb[64];

    const int h    = blockIdx.y;
    const int tid  = threadIdx.x;
    const int warp = tid >> 5;
    const int lane = tid & 31;
    const int g    = lane >> 2;
    const int t    = lane & 3;
    const int qr0  = blockIdx.x * 128 + warp * 16;

    const __half* Qg = &g_Q[(size_t)h * NTOK * HD];
    const __half* Kg = &g_K[(size_t)h * NTOK * HD];
    const __half* Vg = &g_V[(size_t)h * NTOK * HD];
    const float*  pg = &g_peb[h * NTOK];

    const uint32_t* Ksw = (const uint32_t*)Ks;
    const uint32_t* Vtw = (const uint32_t*)Vt;

    // Q fragments resident: 4 k-steps x 4 half2 regs
    uint32_t aq[4][4];
#pragma unroll
    for (int kk = 0; kk < 4; kk++) {
        aq[kk][0] = *(const uint32_t*)&Qg[(qr0 + g) * HD + kk * 16 + 2 * t];
        aq[kk][1] = *(const uint32_t*)&Qg[(qr0 + g + 8) * HD + kk * 16 + 2 * t];
        aq[kk][2] = *(const uint32_t*)&Qg[(qr0 + g) * HD + kk * 16 + 2 * t + 8];
        aq[kk][3] = *(const uint32_t*)&Qg[(qr0 + g + 8) * HD + kk * 16 + 2 * t + 8];
    }

    float oacc[8][4];
#pragma unroll
    for (int nt = 0; nt < 8; nt++)
#pragma unroll
        for (int c = 0; c < 4; c++) oacc[nt][c] = 0.f;
    float m0 = -1e30f, m1 = -1e30f, l0 = 0.f, l1 = 0.f;

    for (int j0 = 0; j0 < NTOK; j0 += 64) {
        // ---- stage K [64 keys][64 feats]: 512 uint4, 2/thread ----
#pragma unroll
        for (int ii = 0; ii < 2; ii++) {
            const int id  = tid + ii * 256;
            const int row = id >> 3;
            const int c8  = (id & 7) << 3;
            *(uint4*)&Ks[row * 72 + c8] =
                *(const uint4*)&Kg[(size_t)(j0 + row) * HD + c8];
        }
        // ---- stage V transposed: Vt[feat][key] ----
        {
            const int kp = tid & 31;         // key pair 0..31
            const int f8 = tid >> 5;         // feat block 0..7
            uint4 va = *(const uint4*)&Vg[(size_t)(j0 + 2 * kp) * HD + f8 * 8];
            uint4 vb = *(const uint4*)&Vg[(size_t)(j0 + 2 * kp + 1) * HD + f8 * 8];
            const __half* ha = (const __half*)&va;
            const __half* hb = (const __half*)&vb;
#pragma unroll
            for (int j = 0; j < 8; j++) {
                __half2 p = __halves2half2(ha[j], hb[j]);
                *(uint32_t*)&Vt[(f8 * 8 + j) * 72 + 2 * kp] =
                    *reinterpret_cast<uint32_t*>(&p);
            }
        }
        if (tid < 64) pb[tid] = pg[j0 + tid];
        __syncthreads();

        // ---- S = Q K^T : 16 x 64, 8 col-blocks ----
        float sacc[8][4];
#pragma unroll
        for (int nt = 0; nt < 8; nt++)
#pragma unroll
            for (int c = 0; c < 4; c++) sacc[nt][c] = 0.f;
#pragma unroll
        for (int kk = 0; kk < 4; kk++) {
#pragma unroll
            for (int nt = 0; nt < 8; nt++) {
                const int key = nt * 8 + g;
                uint32_t bf[2];
                bf[0] = Ksw[key * 36 + kk * 8 + t];
                bf[1] = Ksw[key * 36 + kk * 8 + t + 4];
                mma_f16(sacc[nt], aq[kk], bf);
            }
        }

        // ---- scale + bias, chunk max ----
        float mx0 = -1e30f, mx1 = -1e30f;
#pragma unroll
        for (int nt = 0; nt < 8; nt++) {
            const int c0 = nt * 8 + 2 * t;
            const float pb0 = pb[c0], pb1 = pb[c0 + 1];
            sacc[nt][0] = fmaf(sacc[nt][0], QK_SCALE, pb0);
            sacc[nt][1] = fmaf(sacc[nt][1], QK_SCALE, pb1);
            sacc[nt][2] = fmaf(sacc[nt][2], QK_SCALE, pb0);
            sacc[nt][3] = fmaf(sacc[nt][3], QK_SCALE, pb1);
            mx0 = fmaxf(mx0, fmaxf(sacc[nt][0], sacc[nt][1]));
            mx1 = fmaxf(mx1, fmaxf(sacc[nt][2], sacc[nt][3]));
        }
        mx0 = fmaxf(mx0, __shfl_xor_sync(0xffffffffu, mx0, 1));
        mx0 = fmaxf(mx0, __shfl_xor_sync(0xffffffffu, mx0, 2));
        mx1 = fmaxf(mx1, __shfl_xor_sync(0xffffffffu, mx1, 1));
        mx1 = fmaxf(mx1, __shfl_xor_sync(0xffffffffu, mx1, 2));

        const float mn0 = fmaxf(m0, mx0);
        const float mn1 = fmaxf(m1, mx1);
        const float al0 = __expf(m0 - mn0);
        const float al1 = __expf(m1 - mn1);
        m0 = mn0; m1 = mn1;

        // ---- P = exp(S - m): pack straight into PV A-fragments ----
        float rs0 = 0.f, rs1 = 0.f;
        uint32_t pa[4][4];   // [kv k-step][a-reg]
#pragma unroll
        for (int kv = 0; kv < 4; kv++) {
            float p00a = __expf(sacc[2 * kv][0] - m0);
            float p01a = __expf(sacc[2 * kv][1] - m0);
            float p10a = __expf(sacc[2 * kv][2] - m1);
            float p11a = __expf(sacc[2 * kv][3] - m1);
            float p00b = __expf(sacc[2 * kv + 1][0] - m0);
            float p01b = __expf(sacc[2 * kv + 1][1] - m0);
            float p10b = __expf(sacc[2 * kv + 1][2] - m1);
            float p11b = __expf(sacc[2 * kv + 1][3] - m1);
            rs0 += (p00a + p01a) + (p00b + p01b);
            rs1 += (p10a + p11a) + (p10b + p11b);
            pa[kv][0] = pack2(p00a, p01a);   // row g,   keys 16kv+2t,+1
            pa[kv][1] = pack2(p10a, p11a);   // row g+8
            pa[kv][2] = pack2(p00b, p01b);   // row g,   keys 16kv+8+2t
            pa[kv][3] = pack2(p10b, p11b);   // row g+8
        }
        rs0 += __shfl_xor_sync(0xffffffffu, rs0, 1);
        rs0 += __shfl_xor_sync(0xffffffffu, rs0, 2);
        rs1 += __shfl_xor_sync(0xffffffffu, rs1, 1);
        rs1 += __shfl_xor_sync(0xffffffffu, rs1, 2);
        l0 = l0 * al0 + rs0;
        l1 = l1 * al1 + rs1;

        // ---- rescale O, then O += P(16x64) V(64x64) ----
#pragma unroll
        for (int nt = 0; nt < 8; nt++) {
            oacc[nt][0] *= al0; oacc[nt][1] *= al0;
            oacc[nt][2] *= al1; oacc[nt][3] *= al1;
        }
#pragma unroll
        for (int kv = 0; kv < 4; kv++) {
#pragma unroll
            for (int nt = 0; nt < 8; nt++) {
                const int f = nt * 8 + g;
                uint32_t bf[2];
                bf[0] = Vtw[f * 36 + kv * 8 + t];
                bf[1] = Vtw[f * 36 + kv * 8 + t + 4];
                mma_f16(oacc[nt], pa[kv], bf);
            }
        }
        __syncthreads();   // protect Ks/Vt before next stage
    }

    // ---- normalize + write ----
    const float inv0 = 1.f / l0;
    const float inv1 = 1.f / l1;
#pragma unroll
    for (int nt = 0; nt < 8; nt++) {
        const int d = nt * 8 + 2 * t;
        float2 v0 = {oacc[nt][0] * inv0, oacc[nt][1] * inv0};
        float2 v1 = {oacc[nt][2] * inv1, oacc[nt][3] * inv1};
        *(float2*)&g_AO[(size_t)(qr0 + g) * DM + h * HD + d]     = v0;
        *(float2*)&g_AO[(size_t)(qr0 + g + 8) * DM + h * HD + d] = v1;
    }
}

// ---------------------------------------------------------------------------
extern "C" void kernel_launch(void* const* d_in, const int* in_sizes, int n_in,
                              void* d_out, int out_size) {
    const float* x     = (const float*)d_in[0];
    const float* pe    = (const float*)d_in[1];
    const float* w_qkv = (const float*)d_in[2];
    const float* b_qkv = (const float*)d_in[3];
    const float* w_pe  = (const float*)d_in[4];
    const float* b_pe  = (const float*)d_in[5];
    const float* w_out = (const float*)d_in[6];
    const float* b_out = (const float*)d_in[7];
    float* out = (float*)d_out;

    // QKV projection: 4096x1536, blocks 128x64 -> (32, 24)
    gemm_mma<3 * DM, true, false><<<dim3(32, 24), 256>>>(x, w_qkv, b_qkv, nullptr);

    // pe projection (key-side softmax bias)
    pe_proj<<<NTOK / 256, 256>>>(pe, w_pe, b_pe);

    // flash attention: 32 query blocks x 8 heads (all CTAs co-resident)
    attn_mma<<<dim3(32, NH), 256>>>();

    // output projection: 4096x512 -> (32, 8); A = g_AO selected in device code
    gemm_mma<DM, false, true><<<dim3(32, 8), 256>>>(nullptr, w_out, b_out, out);
}

// round 10
// speedup vs baseline: 6.7294x; 1.3518x over previous
#include <cuda_runtime.h>
#include <cuda_fp16.h>
#include <cstdint>

#define NTOK 4096
#define DM   512
#define DPE  16
#define NH   8
#define HD   64
#define QK_SCALE 0.125f   // 64^-0.5

// Scratch (no allocations allowed)
__device__ __half g_Q[NH * NTOK * HD];   // [h][n][d]  fp16
__device__ __half g_K[NH * NTOK * HD];
__device__ __half g_V[NH * NTOK * HD];
__device__ float  g_peb[NH * NTOK];      // [h][n] key-side softmax bias
__device__ float  g_AO[NTOK * DM];       // attention output, [n][h*64+d]

// ---------------------------------------------------------------------------
// fp16 mma m16n8k16 row.col, f32 accum.
// A: a0=(g,2t),(g,2t+1) a1=(g+8,..) a2=(g,2t+8..) a3=(g+8,2t+8..)
// B: b0=(2t,g),(2t+1,g) b1=(2t+8,g),(2t+9,g)
// C: c0=(g,2t) c1=(g,2t+1) c2=(g+8,2t) c3=(g+8,2t+1)   [g=lane>>2, t=lane&3]
// ---------------------------------------------------------------------------
__device__ __forceinline__ void mma_f16(float d[4], const uint32_t a[4],
                                        const uint32_t b[2]) {
    asm("mma.sync.aligned.m16n8k16.row.col.f32.f16.f16.f32 "
        "{%0,%1,%2,%3}, {%4,%5,%6,%7}, {%8,%9}, {%0,%1,%2,%3};"
        : "+f"(d[0]), "+f"(d[1]), "+f"(d[2]), "+f"(d[3])
        : "r"(a[0]), "r"(a[1]), "r"(a[2]), "r"(a[3]), "r"(b[0]), "r"(b[1]));
}

__device__ __forceinline__ uint32_t pack2(float lo, float hi) {
    __half2 h = __floats2half2_rn(lo, hi);
    return *reinterpret_cast<uint32_t*>(&h);
}

// ---------------------------------------------------------------------------
// fp16 GEMM: C[M x NCOLS] = A[M x 512] * B[512 x NCOLS] + bias
// Block 128x64, 8 warps (4m x 2n), warp tile 32x32, BK=32 (2 k16 steps).
// Register-prefetch double buffering: LDG for tile t+1 issued before compute
// of tile t. B loaded coalesced (float4 along the row) and k-paired into
// half2 [kp][col] layout via shfl_xor(16): lanes<16 hold k=2kp, lanes>=16
// k=2kp+1 for identical cols.
// Conflict-free fragment LDS: As word stride 20 (20g+t distinct mod 32),
// Bp word stride 72 (8t+g distinct mod 32).
// ---------------------------------------------------------------------------
template <int NCOLS, bool QKV_SCATTER, bool A_FROM_GAO>
__global__ __launch_bounds__(256) void gemm_mma(const float* __restrict__ Ain,
                                                const float* __restrict__ B,
                                                const float* __restrict__ bias,
                                                float* __restrict__ C) {
    __shared__ __half   As[128 * 40];   // [row][k]  stride 40 halves (20 words)
    __shared__ uint32_t Bp[16 * 72];    // [kp][col] half2, stride 72 words

    const float* A = A_FROM_GAO ? g_AO : Ain;

    const int row0 = blockIdx.x * 128;
    const int col0 = blockIdx.y * 64;
    const int tid  = threadIdx.x;
    const int warp = tid >> 5;
    const int lane = tid & 31;
    const int g    = lane >> 2;
    const int t    = lane & 3;
    const int wm   = (warp >> 1) * 32;
    const int wn   = (warp & 1) * 32;

    const uint32_t* Asw = (const uint32_t*)As;

    float4 apre[4];
    float4 bpre[2];

    // ---- prologue LDG (tile 0) ----
#pragma unroll
    for (int ii = 0; ii < 4; ii++) {
        const int id = tid + ii * 256;
        const int r  = id >> 3;
        const int c4 = (id & 7) << 2;
        apre[ii] = *(const float4*)&A[(size_t)(row0 + r) * DM + c4];
    }
#pragma unroll
    for (int ii = 0; ii < 2; ii++) {
        const int id = tid + ii * 256;
        const int k  = id >> 4;
        const int c4 = (id & 15) << 2;
        bpre[ii] = *(const float4*)&B[(size_t)k * NCOLS + col0 + c4];
    }

    float acc[2][4][4];
#pragma unroll
    for (int mt = 0; mt < 2; mt++)
#pragma unroll
        for (int nt = 0; nt < 4; nt++)
#pragma unroll
            for (int c = 0; c < 4; c++) acc[mt][nt][c] = 0.f;

    for (int k0 = 0; k0 < DM; k0 += 32) {
        // ---- STS staged tile ----
#pragma unroll
        for (int ii = 0; ii < 4; ii++) {
            const int id = tid + ii * 256;
            const int r  = id >> 3;
            const int c4 = (id & 7) << 2;
            uint2 p;
            p.x = pack2(apre[ii].x, apre[ii].y);
            p.y = pack2(apre[ii].z, apre[ii].w);
            *(uint2*)&As[r * 40 + c4] = p;
        }
#pragma unroll
        for (int ii = 0; ii < 2; ii++) {
            float4 mine = bpre[ii];
            float4 oth;
            oth.x = __shfl_xor_sync(0xffffffffu, mine.x, 16);
            oth.y = __shfl_xor_sync(0xffffffffu, mine.y, 16);
            oth.z = __shfl_xor_sync(0xffffffffu, mine.z, 16);
            oth.w = __shfl_xor_sync(0xffffffffu, mine.w, 16);
            if (lane < 16) {            // holds even k = 2*(warp + 8*ii)
                const int kp = warp + 8 * ii;
                const int c4 = lane << 2;
                uint4 pk;
                pk.x = pack2(mine.x, oth.x);
                pk.y = pack2(mine.y, oth.y);
                pk.z = pack2(mine.z, oth.z);
                pk.w = pack2(mine.w, oth.w);
                *(uint4*)&Bp[kp * 72 + c4] = pk;
            }
        }
        __syncthreads();

        // ---- prefetch LDG for next tile ----
        if (k0 + 32 < DM) {
            const int kn = k0 + 32;
#pragma unroll
            for (int ii = 0; ii < 4; ii++) {
                const int id = tid + ii * 256;
                const int r  = id >> 3;
                const int c4 = (id & 7) << 2;
                apre[ii] = *(const float4*)&A[(size_t)(row0 + r) * DM + kn + c4];
            }
#pragma unroll
            for (int ii = 0; ii < 2; ii++) {
                const int id = tid + ii * 256;
                const int k  = id >> 4;
                const int c4 = (id & 15) << 2;
                bpre[ii] = *(const float4*)&B[(size_t)(kn + k) * NCOLS + col0 + c4];
            }
        }

        // ---- compute: 2 k16 steps ----
#pragma unroll
        for (int ks = 0; ks < 2; ks++) {
            uint32_t af[2][4];
#pragma unroll
            for (int mt = 0; mt < 2; mt++) {
                const int r = wm + mt * 16 + g;
                af[mt][0] = Asw[r * 20 + ks * 8 + t];
                af[mt][1] = Asw[(r + 8) * 20 + ks * 8 + t];
                af[mt][2] = Asw[r * 20 + ks * 8 + t + 4];
                af[mt][3] = Asw[(r + 8) * 20 + ks * 8 + t + 4];
            }
            uint32_t bf[4][2];
#pragma unroll
            for (int nt = 0; nt < 4; nt++) {
                const int c = wn + nt * 8 + g;
                bf[nt][0] = Bp[(ks * 8 + t) * 72 + c];
                bf[nt][1] = Bp[(ks * 8 + t + 4) * 72 + c];
            }
#pragma unroll
            for (int mt = 0; mt < 2; mt++)
#pragma unroll
                for (int nt = 0; nt < 4; nt++)
                    mma_f16(acc[mt][nt], af[mt], bf[nt]);
        }
        __syncthreads();
    }

    // ---- epilogue ----
#pragma unroll
    for (int mt = 0; mt < 2; mt++) {
#pragma unroll
        for (int nt = 0; nt < 4; nt++) {
            const int cc = wn + nt * 8 + 2 * t;
            const float b0 = bias[col0 + cc];
            const float b1 = bias[col0 + cc + 1];
            const int r0 = row0 + wm + mt * 16 + g;
            if (QKV_SCATTER) {
                const int part = blockIdx.y >> 3;        // 0=Q,1=K,2=V
                const int h    = blockIdx.y & 7;
                __half* dst = (part == 0) ? g_Q : (part == 1) ? g_K : g_V;
                *(uint32_t*)&dst[((size_t)h * NTOK + r0) * HD + cc] =
                    pack2(acc[mt][nt][0] + b0, acc[mt][nt][1] + b1);
                *(uint32_t*)&dst[((size_t)h * NTOK + r0 + 8) * HD + cc] =
                    pack2(acc[mt][nt][2] + b0, acc[mt][nt][3] + b1);
            } else {
                const int c = col0 + cc;
                float2 v0 = {acc[mt][nt][0] + b0, acc[mt][nt][1] + b1};
                float2 v1 = {acc[mt][nt][2] + b0, acc[mt][nt][3] + b1};
                *(float2*)&C[(size_t)r0 * NCOLS + c]       = v0;
                *(float2*)&C[(size_t)(r0 + 8) * NCOLS + c] = v1;
            }
        }
    }
}

// ---------------------------------------------------------------------------
// pe projection: peb[h][n] = sum_k pe[n][k] * w_pe[k][h] + b_pe[h]
// ---------------------------------------------------------------------------
__global__ void pe_proj(const float* __restrict__ pe,
                        const float* __restrict__ wpe,
                        const float* __restrict__ bpe) {
    const int n = blockIdx.x * 256 + threadIdx.x;
    if (n >= NTOK) return;
    float pv[DPE];
#pragma unroll
    for (int k = 0; k < DPE; k++) pv[k] = pe[n * DPE + k];
#pragma unroll
    for (int h = 0; h < NH; h++) {
        float s = bpe[h];
#pragma unroll
        for (int k = 0; k < DPE; k++) s += pv[k] * wpe[k * NH + h];
        g_peb[h * NTOK + n] = s;
    }
}

// ---------------------------------------------------------------------------
// fp16 flash attention, 32 query rows per warp (2 m-tiles).
// bias[h,i,j] = p[j,h] - p[i,h]: -p[i,h] cancels in softmax over j.
// CTA: 256 thr / 8 warps x 32 rows = 256 rows; grid (16, 8) = 128 CTAs ->
// single wave on 148 SMs. K/V b-fragments shared across both m-tiles
// (halves smem fragment traffic per mma). P stays in registers (fp16 C-layout
// == A-layout). Next chunk's K/V/pb prefetched into registers during compute.
// ---------------------------------------------------------------------------
__global__ __launch_bounds__(256, 1) void attn_mma() {
    __shared__ __half Ks[64 * 72];     // [key][feat]
    __shared__ __half Vt[64 * 72];     // [feat][key]
    __shared__ float  pb[64];

    const int h    = blockIdx.y;
    const int tid  = threadIdx.x;
    const int warp = tid >> 5;
    const int lane = tid & 31;
    const int g    = lane >> 2;
    const int t    = lane & 3;
    const int qr0  = blockIdx.x * 256 + warp * 32;

    const __half* Qg = &g_Q[(size_t)h * NTOK * HD];
    const __half* Kg = &g_K[(size_t)h * NTOK * HD];
    const __half* Vg = &g_V[(size_t)h * NTOK * HD];
    const float*  pg = &g_peb[h * NTOK];

    const uint32_t* Ksw = (const uint32_t*)Ks;
    const uint32_t* Vtw = (const uint32_t*)Vt;

    // Q fragments resident: 2 m-tiles x 4 k-steps x 4 regs
    uint32_t aq[2][4][4];
#pragma unroll
    for (int mt = 0; mt < 2; mt++) {
        const int r = qr0 + mt * 16 + g;
#pragma unroll
        for (int kk = 0; kk < 4; kk++) {
            aq[mt][kk][0] = *(const uint32_t*)&Qg[(size_t)r * HD + kk * 16 + 2 * t];
            aq[mt][kk][1] = *(const uint32_t*)&Qg[(size_t)(r + 8) * HD + kk * 16 + 2 * t];
            aq[mt][kk][2] = *(const uint32_t*)&Qg[(size_t)r * HD + kk * 16 + 2 * t + 8];
            aq[mt][kk][3] = *(const uint32_t*)&Qg[(size_t)(r + 8) * HD + kk * 16 + 2 * t + 8];
        }
    }

    float oacc[2][8][4];
#pragma unroll
    for (int mt = 0; mt < 2; mt++)
#pragma unroll
        for (int nt = 0; nt < 8; nt++)
#pragma unroll
            for (int c = 0; c < 4; c++) oacc[mt][nt][c] = 0.f;
    float m[2][2] = {{-1e30f, -1e30f}, {-1e30f, -1e30f}};
    float l[2][2] = {{0.f, 0.f}, {0.f, 0.f}};

    // prefetch registers for K/V/pb staging
    uint4 kpre[2], vpa, vpb;
    float pbpre = 0.f;
    const int krow0 = tid >> 3;            // 0..31
    const int kc8   = (tid & 7) << 3;      // 0..56
    const int vkp   = lane;                // key pair 0..31 (warp-uniform feat)
    const int vf8   = warp;                // feat block 0..7

    // prologue LDG (chunk 0)
    kpre[0] = *(const uint4*)&Kg[(size_t)krow0 * HD + kc8];
    kpre[1] = *(const uint4*)&Kg[(size_t)(krow0 + 32) * HD + kc8];
    vpa = *(const uint4*)&Vg[(size_t)(2 * vkp) * HD + vf8 * 8];
    vpb = *(const uint4*)&Vg[(size_t)(2 * vkp + 1) * HD + vf8 * 8];
    if (tid < 64) pbpre = pg[tid];

    for (int j0 = 0; j0 < NTOK; j0 += 64) {
        // ---- STS staged chunk ----
        *(uint4*)&Ks[krow0 * 72 + kc8]        = kpre[0];
        *(uint4*)&Ks[(krow0 + 32) * 72 + kc8] = kpre[1];
        {
            const __half* ha = (const __half*)&vpa;
            const __half* hb = (const __half*)&vpb;
#pragma unroll
            for (int j = 0; j < 8; j++) {
                __half2 p = __halves2half2(ha[j], hb[j]);
                *(uint32_t*)&Vt[(vf8 * 8 + j) * 72 + 2 * vkp] =
                    *reinterpret_cast<uint32_t*>(&p);
            }
        }
        if (tid < 64) pb[tid] = pbpre;
        __syncthreads();

        // ---- prefetch next chunk (wrapped; extra loads harmless) ----
        {
            const int jn = (j0 + 64) & (NTOK - 1);
            kpre[0] = *(const uint4*)&Kg[(size_t)(jn + krow0) * HD + kc8];
            kpre[1] = *(const uint4*)&Kg[(size_t)(jn + krow0 + 32) * HD + kc8];
            vpa = *(const uint4*)&Vg[(size_t)(jn + 2 * vkp) * HD + vf8 * 8];
            vpb = *(const uint4*)&Vg[(size_t)(jn + 2 * vkp + 1) * HD + vf8 * 8];
            if (tid < 64) pbpre = pg[jn + tid];
        }

        // ---- S = Q K^T : 2 x (16 x 64); K b-frags shared across m-tiles ----
        float sacc[2][8][4];
#pragma unroll
        for (int mt = 0; mt < 2; mt++)
#pragma unroll
            for (int nt = 0; nt < 8; nt++)
#pragma unroll
                for (int c = 0; c < 4; c++) sacc[mt][nt][c] = 0.f;
#pragma unroll
        for (int kk = 0; kk < 4; kk++) {
#pragma unroll
            for (int nt = 0; nt < 8; nt++) {
                const int key = nt * 8 + g;
                uint32_t bf[2];
                bf[0] = Ksw[key * 36 + kk * 8 + t];
                bf[1] = Ksw[key * 36 + kk * 8 + t + 4];
                mma_f16(sacc[0][nt], aq[0][kk], bf);
                mma_f16(sacc[1][nt], aq[1][kk], bf);
            }
        }

        // ---- softmax per m-tile; pack P into PV A-fragments ----
        uint32_t pa[2][4][4];
#pragma unroll
        for (int mt = 0; mt < 2; mt++) {
            float mx0 = -1e30f, mx1 = -1e30f;
#pragma unroll
            for (int nt = 0; nt < 8; nt++) {
                const int c0 = nt * 8 + 2 * t;
                const float pb0 = pb[c0], pb1 = pb[c0 + 1];
                sacc[mt][nt][0] = fmaf(sacc[mt][nt][0], QK_SCALE, pb0);
                sacc[mt][nt][1] = fmaf(sacc[mt][nt][1], QK_SCALE, pb1);
                sacc[mt][nt][2] = fmaf(sacc[mt][nt][2], QK_SCALE, pb0);
                sacc[mt][nt][3] = fmaf(sacc[mt][nt][3], QK_SCALE, pb1);
                mx0 = fmaxf(mx0, fmaxf(sacc[mt][nt][0], sacc[mt][nt][1]));
                mx1 = fmaxf(mx1, fmaxf(sacc[mt][nt][2], sacc[mt][nt][3]));
            }
            mx0 = fmaxf(mx0, __shfl_xor_sync(0xffffffffu, mx0, 1));
            mx0 = fmaxf(mx0, __shfl_xor_sync(0xffffffffu, mx0, 2));
            mx1 = fmaxf(mx1, __shfl_xor_sync(0xffffffffu, mx1, 1));
            mx1 = fmaxf(mx1, __shfl_xor_sync(0xffffffffu, mx1, 2));

            const float mn0 = fmaxf(m[mt][0], mx0);
            const float mn1 = fmaxf(m[mt][1], mx1);
            const float al0 = __expf(m[mt][0] - mn0);
            const float al1 = __expf(m[mt][1] - mn1);
            m[mt][0] = mn0; m[mt][1] = mn1;

            float rs0 = 0.f, rs1 = 0.f;
#pragma unroll
            for (int kv = 0; kv < 4; kv++) {
                float p00a = __expf(sacc[mt][2 * kv][0] - mn0);
                float p01a = __expf(sacc[mt][2 * kv][1] - mn0);
                float p10a = __expf(sacc[mt][2 * kv][2] - mn1);
                float p11a = __expf(sacc[mt][2 * kv][3] - mn1);
                float p00b = __expf(sacc[mt][2 * kv + 1][0] - mn0);
                float p01b = __expf(sacc[mt][2 * kv + 1][1] - mn0);
                float p10b = __expf(sacc[mt][2 * kv + 1][2] - mn1);
                float p11b = __expf(sacc[mt][2 * kv + 1][3] - mn1);
                rs0 += (p00a + p01a) + (p00b + p01b);
                rs1 += (p10a + p11a) + (p10b + p11b);
                pa[mt][kv][0] = pack2(p00a, p01a);
                pa[mt][kv][1] = pack2(p10a, p11a);
                pa[mt][kv][2] = pack2(p00b, p01b);
                pa[mt][kv][3] = pack2(p10b, p11b);
            }
            rs0 += __shfl_xor_sync(0xffffffffu, rs0, 1);
            rs0 += __shfl_xor_sync(0xffffffffu, rs0, 2);
            rs1 += __shfl_xor_sync(0xffffffffu, rs1, 1);
            rs1 += __shfl_xor_sync(0xffffffffu, rs1, 2);
            l[mt][0] = l[mt][0] * al0 + rs0;
            l[mt][1] = l[mt][1] * al1 + rs1;

#pragma unroll
            for (int nt = 0; nt < 8; nt++) {
                oacc[mt][nt][0] *= al0; oacc[mt][nt][1] *= al0;
                oacc[mt][nt][2] *= al1; oacc[mt][nt][3] *= al1;
            }
        }

        // ---- O += P V : V b-frags shared across m-tiles ----
#pragma unroll
        for (int kv = 0; kv < 4; kv++) {
#pragma unroll
            for (int nt = 0; nt < 8; nt++) {
                const int f = nt * 8 + g;
                uint32_t bf[2];
                bf[0] = Vtw[f * 36 + kv * 8 + t];
                bf[1] = Vtw[f * 36 + kv * 8 + t + 4];
                mma_f16(oacc[0][nt], pa[0][kv], bf);
                mma_f16(oacc[1][nt], pa[1][kv], bf);
            }
        }
        __syncthreads();   // protect Ks/Vt before next STS
    }

    // ---- normalize + write ----
#pragma unroll
    for (int mt = 0; mt < 2; mt++) {
        const float inv0 = 1.f / l[mt][0];
        const float inv1 = 1.f / l[mt][1];
        const int r = qr0 + mt * 16 + g;
#pragma unroll
        for (int nt = 0; nt < 8; nt++) {
            const int d = nt * 8 + 2 * t;
            float2 v0 = {oacc[mt][nt][0] * inv0, oacc[mt][nt][1] * inv0};
            float2 v1 = {oacc[mt][nt][2] * inv1, oacc[mt][nt][3] * inv1};
            *(float2*)&g_AO[(size_t)r * DM + h * HD + d]       = v0;
            *(float2*)&g_AO[(size_t)(r + 8) * DM + h * HD + d] = v1;
        }
    }
}

// ---------------------------------------------------------------------------
extern "C" void kernel_launch(void* const* d_in, const int* in_sizes, int n_in,
                              void* d_out, int out_size) {
    const float* x     = (const float*)d_in[0];
    const float* pe    = (const float*)d_in[1];
    const float* w_qkv = (const float*)d_in[2];
    const float* b_qkv = (const float*)d_in[3];
    const float* w_pe  = (const float*)d_in[4];
    const float* b_pe  = (const float*)d_in[5];
    const float* w_out = (const float*)d_in[6];
    const float* b_out = (const float*)d_in[7];
    float* out = (float*)d_out;

    // QKV projection: 4096x1536, blocks 128x64 -> (32, 24)
    gemm_mma<3 * DM, true, false><<<dim3(32, 24), 256>>>(x, w_qkv, b_qkv, nullptr);

    // pe projection (key-side softmax bias)
    pe_proj<<<NTOK / 256, 256>>>(pe, w_pe, b_pe);

    // flash attention: 16 query blocks x 8 heads = 128 CTAs (single wave)
    attn_mma<<<dim3(16, NH), 256>>>();

    // output projection: 4096x512 -> (32, 8); A = g_AO selected in device code
    gemm_mma<DM, false, true><<<dim3(32, 8), 256>>>(nullptr, w_out, b_out, out);
}